// round 7
// baseline (speedup 1.0000x reference)
#include <cuda_runtime.h>
#include <cstddef>

#define NTOK   8192      // B*S
#define DMODEL 1024
#define NFF    2048

// ---------------- scratch (no allocations allowed -> device globals) ----------------
__device__ float g_xn [NTOK * DMODEL];
__device__ float g_q  [NTOK * DMODEL];
__device__ float g_k  [NTOK * DMODEL];
__device__ float g_v  [NTOK * DMODEL];
__device__ float g_att[NTOK * DMODEL];
__device__ float g_h  [NTOK * DMODEL];
__device__ float g_ff [NTOK * NFF];

// =====================================================================
// LayerNorm: one block per row (1024 elements), 256 threads x 4 elems
// =====================================================================
__global__ __launch_bounds__(256)
void ln_kernel(const float* __restrict__ x, const float* __restrict__ g,
               const float* __restrict__ b, float eps, float* __restrict__ out)
{
    const int tid = threadIdx.x;
    const float* xr = x + (size_t)blockIdx.x * DMODEL;
    float* orow = out + (size_t)blockIdx.x * DMODEL;

    float v[4];
    float s = 0.f;
#pragma unroll
    for (int i = 0; i < 4; i++) { v[i] = xr[tid + 256 * i]; s += v[i]; }

    __shared__ float red[8];
    __shared__ float stat[2];

#pragma unroll
    for (int o = 16; o; o >>= 1) s += __shfl_xor_sync(0xffffffffu, s, o);
    if ((tid & 31) == 0) red[tid >> 5] = s;
    __syncthreads();
    if (tid == 0) {
        float t = 0.f;
#pragma unroll
        for (int i = 0; i < 8; i++) t += red[i];
        stat[0] = t * (1.f / DMODEL);
    }
    __syncthreads();
    const float mu = stat[0];

    float s2 = 0.f;
#pragma unroll
    for (int i = 0; i < 4; i++) { float d = v[i] - mu; s2 += d * d; }
#pragma unroll
    for (int o = 16; o; o >>= 1) s2 += __shfl_xor_sync(0xffffffffu, s2, o);
    if ((tid & 31) == 0) red[tid >> 5] = s2;
    __syncthreads();
    if (tid == 0) {
        float t = 0.f;
#pragma unroll
        for (int i = 0; i < 8; i++) t += red[i];
        stat[1] = rsqrtf(t * (1.f / DMODEL) + eps);
    }
    __syncthreads();
    const float rstd = stat[1];

#pragma unroll
    for (int i = 0; i < 4; i++) {
        const int c = tid + 256 * i;
        orow[c] = (v[i] - mu) * rstd * g[c] + b[c];
    }
}

// =====================================================================
// SGEMM core: 128x128 block tile, BK=16, 256 threads, 8x8 micro-tile,
// DOUBLE-BUFFERED smem (prefetch next K-tile into regs during compute).
//   MODE 0: C = AB
//   MODE 1: C = AB + res
//   MODE 2: C = relu(AB + bias)
//   MODE 3: C = AB + bias + res   (res may alias C; each elem touched once)
// M,N multiples of 128; K multiple of 16 (true for all call sites).
// =====================================================================
template <int MODE>
__device__ __forceinline__
void sgemm_body(const float* __restrict__ A, const float* __restrict__ B,
                const float* __restrict__ bias, const float* res,
                float* C, int M, int N, int K, int bm, int bn)
{
    __shared__ float As[2][16][132];   // transposed A tile, padded pitch
    __shared__ float Bs[2][16][128];

    const int tid = threadIdx.x;
    const int tx = tid & 15;        // col group (8 cols)
    const int ty = tid >> 4;        // row group (8 rows)

    float acc[8][8];
#pragma unroll
    for (int i = 0; i < 8; i++)
#pragma unroll
        for (int j = 0; j < 8; j++) acc[i][j] = 0.f;

    // loader indices
    const int ar = tid >> 2;          // 0..63  (A tile row, +64 second half)
    const int ac = (tid & 3) << 2;    // 0,4,8,12 (A tile col group of 4)
    const int br = tid >> 5;          // 0..7   (B tile row, +8 second half)
    const int bc = (tid & 31) << 2;   // 0..124 (B tile col group of 4)

    const float* Aptr = A + (size_t)bm * K;
    const float* Bptr = B + bn;

    float4 fa[2], fb[2];

    // --- preload tile 0 into buffer 0 ---
#pragma unroll
    for (int i = 0; i < 2; i++)
        fa[i] = *(const float4*)(Aptr + (size_t)(ar + i * 64) * K + ac);
#pragma unroll
    for (int i = 0; i < 2; i++)
        fb[i] = *(const float4*)(Bptr + (size_t)(br + i * 8) * N + bc);
#pragma unroll
    for (int i = 0; i < 2; i++) {
        const int r = ar + i * 64;
        As[0][ac + 0][r] = fa[i].x;
        As[0][ac + 1][r] = fa[i].y;
        As[0][ac + 2][r] = fa[i].z;
        As[0][ac + 3][r] = fa[i].w;
    }
#pragma unroll
    for (int i = 0; i < 2; i++)
        *(float4*)&Bs[0][br + i * 8][bc] = fb[i];
    __syncthreads();

    int buf = 0;
    for (int k0 = 0; k0 < K; k0 += 16) {
        const bool has_next = (k0 + 16) < K;

        // prefetch next tile into registers (latency hidden behind compute)
        if (has_next) {
            const int kn = k0 + 16;
#pragma unroll
            for (int i = 0; i < 2; i++)
                fa[i] = *(const float4*)(Aptr + (size_t)(ar + i * 64) * K + kn + ac);
#pragma unroll
            for (int i = 0; i < 2; i++)
                fb[i] = *(const float4*)(Bptr + (size_t)(kn + br + i * 8) * N + bc);
        }

        // compute on current buffer
#pragma unroll
        for (int k = 0; k < 16; k++) {
            float a[8], bb[8];
            *(float4*)&a[0]  = *(const float4*)&As[buf][k][ty * 8];
            *(float4*)&a[4]  = *(const float4*)&As[buf][k][ty * 8 + 4];
            *(float4*)&bb[0] = *(const float4*)&Bs[buf][k][tx * 8];
            *(float4*)&bb[4] = *(const float4*)&Bs[buf][k][tx * 8 + 4];
#pragma unroll
            for (int i = 0; i < 8; i++)
#pragma unroll
                for (int j = 0; j < 8; j++) acc[i][j] += a[i] * bb[j];
        }

        // store prefetched tile into the other buffer (no one reads it yet)
        if (has_next) {
            const int nb = buf ^ 1;
#pragma unroll
            for (int i = 0; i < 2; i++) {
                const int r = ar + i * 64;
                As[nb][ac + 0][r] = fa[i].x;
                As[nb][ac + 1][r] = fa[i].y;
                As[nb][ac + 2][r] = fa[i].z;
                As[nb][ac + 3][r] = fa[i].w;
            }
#pragma unroll
            for (int i = 0; i < 2; i++)
                *(float4*)&Bs[nb][br + i * 8][bc] = fb[i];
        }
        __syncthreads();
        buf ^= 1;
    }

    const int crow = bm + ty * 8;
    const int ccol = bn + tx * 8;
#pragma unroll
    for (int i = 0; i < 8; i++) {
        const size_t off = (size_t)(crow + i) * N + ccol;
#pragma unroll
        for (int j = 0; j < 8; j++) {
            float val = acc[i][j];
            if (MODE == 1) val += res[off + j];
            if (MODE == 2) { val += bias[ccol + j]; val = fmaxf(val, 0.f); }
            if (MODE == 3) { val += bias[ccol + j] + res[off + j]; }
            C[off + j] = val;
        }
    }
}

template <int MODE>
__global__ __launch_bounds__(256)
void sgemm_kernel(const float* __restrict__ A, const float* __restrict__ B,
                  const float* __restrict__ bias, const float* res,
                  float* C, int M, int N, int K)
{
    sgemm_body<MODE>(A, B, bias, res, C, M, N, K,
                     blockIdx.y * 128, blockIdx.x * 128);
}

// Fused QKV: blockIdx.z picks (W, out). One launch, 3x the blocks ->
// fewer wave-quantization tails than 3 serialized launches.
__global__ __launch_bounds__(256)
void sgemm_qkv_kernel(const float* __restrict__ A,
                      const float* __restrict__ B0, const float* __restrict__ B1,
                      const float* __restrict__ B2,
                      float* C0, float* C1, float* C2)
{
    const float* B = (blockIdx.z == 0) ? B0 : (blockIdx.z == 1) ? B1 : B2;
    float*       C = (blockIdx.z == 0) ? C0 : (blockIdx.z == 1) ? C1 : C2;
    sgemm_body<0>(A, B, nullptr, nullptr, C, NTOK, DMODEL, DMODEL,
                  blockIdx.y * 128, blockIdx.x * 128);
}

// =====================================================================
// Flash attention, fp32. Per block: one (b,h) head, 64-query tile.
// 256 threads as 16(ty: q)x16(tx: k/dv); thread owns q in {ty+16i},
// k/dv in {tx+16j} -> conflict-free smem access patterns (see pitches).
// Q prescaled by 1/sqrt(DK)=0.125 at load.
// =====================================================================
#define ATT_SMEM_FLOATS (64 * 64 + 64 * 68 + 64 * 64 + 64 * 65)
#define ATT_SMEM_BYTES  (ATT_SMEM_FLOATS * 4)

__global__ __launch_bounds__(256)
void attn_kernel(const float* __restrict__ Q, const float* __restrict__ Kg,
                 const float* __restrict__ Vg, float* __restrict__ O)
{
    extern __shared__ float sm[];
    float (*Qs)[64] = (float (*)[64])sm;                           // [64][64]
    float (*Ks)[68] = (float (*)[68])(sm + 64 * 64);               // [64][68]
    float (*Vs)[64] = (float (*)[64])(sm + 64 * 64 + 64 * 68);     // [64][64]
    float (*Ps)[65] = (float (*)[65])(sm + 64 * 64 + 64 * 68 + 64 * 64); // [64][65]

    const int tid = threadIdx.x;
    const int tx = tid & 15;
    const int ty = tid >> 4;
    const int qt = blockIdx.x;              // 0..31 query tiles
    const int bh = blockIdx.y;              // 0..63 (b*16+h)
    const size_t base = ((size_t)(bh >> 4) * 2048) * DMODEL + (size_t)(bh & 15) * 64;
    const float* Qp = Q  + base + (size_t)qt * 64 * DMODEL;
    const float* Kp = Kg + base;
    const float* Vp = Vg + base;
    float*       Op = O  + base + (size_t)qt * 64 * DMODEL;

    // load Q tile (64x64), prescaled
    {
        const int r0 = tid >> 4;
        const int d  = (tid & 15) * 4;
#pragma unroll
        for (int it = 0; it < 4; it++) {
            const int r = r0 + it * 16;
            float4 f = *(const float4*)(Qp + (size_t)r * DMODEL + d);
            Qs[r][d + 0] = f.x * 0.125f;
            Qs[r][d + 1] = f.y * 0.125f;
            Qs[r][d + 2] = f.z * 0.125f;
            Qs[r][d + 3] = f.w * 0.125f;
        }
    }

    float acc[4][4];
#pragma unroll
    for (int i = 0; i < 4; i++)
#pragma unroll
        for (int j = 0; j < 4; j++) acc[i][j] = 0.f;
    float mrun[4], lrun[4];
#pragma unroll
    for (int i = 0; i < 4; i++) { mrun[i] = -1e30f; lrun[i] = 0.f; }

    for (int kt = 0; kt < 32; kt++) {
        __syncthreads();  // prev PV done (Vs/Ps free); iter 0: orders Qs stores too
        {
            const float* Kt = Kp + (size_t)(kt * 64) * DMODEL;
            const float* Vt = Vp + (size_t)(kt * 64) * DMODEL;
            const int r0 = tid >> 4;
            const int d  = (tid & 15) * 4;
#pragma unroll
            for (int it = 0; it < 4; it++) {
                const int r = r0 + it * 16;
                *(float4*)&Ks[r][d] = *(const float4*)(Kt + (size_t)r * DMODEL + d);
                *(float4*)&Vs[r][d] = *(const float4*)(Vt + (size_t)r * DMODEL + d);
            }
        }
        __syncthreads();

        // S = Qs @ Ks^T  (scores, prescaled)
        float s[4][4];
#pragma unroll
        for (int i = 0; i < 4; i++)
#pragma unroll
            for (int j = 0; j < 4; j++) s[i][j] = 0.f;
#pragma unroll
        for (int d = 0; d < 64; d += 4) {
            float4 a[4], b[4];
#pragma unroll
            for (int i = 0; i < 4; i++) a[i] = *(const float4*)&Qs[ty + 16 * i][d];
#pragma unroll
            for (int j = 0; j < 4; j++) b[j] = *(const float4*)&Ks[tx + 16 * j][d];
#pragma unroll
            for (int i = 0; i < 4; i++)
#pragma unroll
                for (int j = 0; j < 4; j++) {
                    s[i][j] += a[i].x * b[j].x;
                    s[i][j] += a[i].y * b[j].y;
                    s[i][j] += a[i].z * b[j].z;
                    s[i][j] += a[i].w * b[j].w;
                }
        }

        // online softmax (row state replicated across the 16 tx lanes of a row)
#pragma unroll
        for (int i = 0; i < 4; i++) {
            float mt = fmaxf(fmaxf(s[i][0], s[i][1]), fmaxf(s[i][2], s[i][3]));
#pragma unroll
            for (int o = 8; o; o >>= 1) mt = fmaxf(mt, __shfl_xor_sync(0xffffffffu, mt, o));
            const float mnew = fmaxf(mrun[i], mt);
            const float corr = __expf(mrun[i] - mnew);
            mrun[i] = mnew;
            float p[4];
            float ls = 0.f;
#pragma unroll
            for (int j = 0; j < 4; j++) { p[j] = __expf(s[i][j] - mnew); ls += p[j]; }
#pragma unroll
            for (int o = 8; o; o >>= 1) ls += __shfl_xor_sync(0xffffffffu, ls, o);
            lrun[i] = lrun[i] * corr + ls;
#pragma unroll
            for (int j = 0; j < 4; j++) acc[i][j] *= corr;
#pragma unroll
            for (int j = 0; j < 4; j++) Ps[ty + 16 * i][tx + 16 * j] = p[j];
        }
        __syncthreads();

        // acc += P @ V
#pragma unroll 8
        for (int k = 0; k < 64; k++) {
            float pv[4], vv[4];
#pragma unroll
            for (int i = 0; i < 4; i++) pv[i] = Ps[ty + 16 * i][k];
#pragma unroll
            for (int j = 0; j < 4; j++) vv[j] = Vs[k][tx + 16 * j];
#pragma unroll
            for (int i = 0; i < 4; i++)
#pragma unroll
                for (int j = 0; j < 4; j++) acc[i][j] += pv[i] * vv[j];
        }
    }

#pragma unroll
    for (int i = 0; i < 4; i++) {
        const float inv = 1.f / lrun[i];
#pragma unroll
        for (int j = 0; j < 4; j++)
            Op[(size_t)(ty + 16 * i) * DMODEL + tx + 16 * j] = acc[i][j] * inv;
    }
}

// =====================================================================
// launch
// =====================================================================
extern "C" void kernel_launch(void* const* d_in, const int* in_sizes, int n_in,
                              void* d_out, int out_size)
{
    (void)in_sizes; (void)n_in; (void)out_size;
    const float* x    = (const float*)d_in[0];
    const float* Wq   = (const float*)d_in[1];
    const float* Wk   = (const float*)d_in[2];
    const float* Wv   = (const float*)d_in[3];
    const float* Wo   = (const float*)d_in[4];
    const float* ln1g = (const float*)d_in[5];
    const float* ln1b = (const float*)d_in[6];
    const float* fc1w = (const float*)d_in[7];
    const float* fc1b = (const float*)d_in[8];
    const float* fc2w = (const float*)d_in[9];
    const float* fc2b = (const float*)d_in[10];
    const float* ln2g = (const float*)d_in[11];
    const float* ln2b = (const float*)d_in[12];
    float* out = (float*)d_out;

    void *pxn, *pq, *pk, *pv, *patt, *ph, *pff;
    cudaGetSymbolAddress(&pxn,  g_xn);
    cudaGetSymbolAddress(&pq,   g_q);
    cudaGetSymbolAddress(&pk,   g_k);
    cudaGetSymbolAddress(&pv,   g_v);
    cudaGetSymbolAddress(&patt, g_att);
    cudaGetSymbolAddress(&ph,   g_h);
    cudaGetSymbolAddress(&pff,  g_ff);
    float* xn  = (float*)pxn;
    float* q   = (float*)pq;
    float* k   = (float*)pk;
    float* v   = (float*)pv;
    float* att = (float*)patt;
    float* h   = (float*)ph;
    float* ff  = (float*)pff;

    // opt-in smem limit for the attention kernel (idempotent; not a stream op,
    // legal under graph capture).
    cudaFuncSetAttribute(attn_kernel, cudaFuncAttributeMaxDynamicSharedMemorySize,
                         ATT_SMEM_BYTES);

    // 1) LN1
    ln_kernel<<<NTOK, 256>>>(x, ln1g, ln1b, 1e-5f, xn);

    // 2) fused QKV projections: one launch, z in {0,1,2}
    dim3 gQKV(DMODEL / 128, NTOK / 128, 3);   // (8, 64, 3)
    sgemm_qkv_kernel<<<gQKV, 256>>>(xn, Wq, Wk, Wv, q, k, v);

    // 3) attention (flash): grid = (S/64 query tiles, B*H heads)
    attn_kernel<<<dim3(32, 64), 256, ATT_SMEM_BYTES>>>(q, k, v, att);

    // 4) out = att @ Wo + x   -> d_out
    dim3 gD(DMODEL / 128, NTOK / 128);        // (8, 64)
    sgemm_kernel<1><<<gD, 256>>>(att, Wo, nullptr, x, out, NTOK, DMODEL, DMODEL);

    // 5) LN2 (eps = 1e-6)
    ln_kernel<<<NTOK, 256>>>(out, ln2g, ln2b, 1e-6f, h);

    // 6) ff = relu(h @ fc1_w + fc1_b)
    dim3 gF(NFF / 128, NTOK / 128);           // (16, 64)
    sgemm_kernel<2><<<gF, 256>>>(h, fc1w, fc1b, nullptr, ff, NTOK, NFF, DMODEL);

    // 7) d_out = d_out + ff @ fc2_w + fc2_b   (in-place accumulate)
    sgemm_kernel<3><<<gD, 256>>>(ff, fc2w, fc2b, out, out, NTOK, DMODEL, NFF);
}

// round 8
// speedup vs baseline: 1.6388x; 1.6388x over previous
#include <cuda_runtime.h>
#include <cuda_bf16.h>
#include <cstdint>
#include <cstddef>

#define NTOK   8192      // B*S
#define DMODEL 1024
#define NFF    2048

// ---------------- scratch (no allocations allowed -> device globals) ----------------
__device__ float g_xn [NTOK * DMODEL];
__device__ float g_q  [NTOK * DMODEL];
__device__ float g_k  [NTOK * DMODEL];
__device__ float g_v  [NTOK * DMODEL];
__device__ float g_att[NTOK * DMODEL];
__device__ float g_h  [NTOK * DMODEL];
__device__ float g_ff [NTOK * NFF];

// =====================================================================
// LayerNorm: one block per row (1024 elements), 256 threads x 4 elems
// =====================================================================
__global__ __launch_bounds__(256)
void ln_kernel(const float* __restrict__ x, const float* __restrict__ g,
               const float* __restrict__ b, float eps, float* __restrict__ out)
{
    const int tid = threadIdx.x;
    const float* xr = x + (size_t)blockIdx.x * DMODEL;
    float* orow = out + (size_t)blockIdx.x * DMODEL;

    float v[4];
    float s = 0.f;
#pragma unroll
    for (int i = 0; i < 4; i++) { v[i] = xr[tid + 256 * i]; s += v[i]; }

    __shared__ float red[8];
    __shared__ float stat[2];

#pragma unroll
    for (int o = 16; o; o >>= 1) s += __shfl_xor_sync(0xffffffffu, s, o);
    if ((tid & 31) == 0) red[tid >> 5] = s;
    __syncthreads();
    if (tid == 0) {
        float t = 0.f;
#pragma unroll
        for (int i = 0; i < 8; i++) t += red[i];
        stat[0] = t * (1.f / DMODEL);
    }
    __syncthreads();
    const float mu = stat[0];

    float s2 = 0.f;
#pragma unroll
    for (int i = 0; i < 4; i++) { float d = v[i] - mu; s2 += d * d; }
#pragma unroll
    for (int o = 16; o; o >>= 1) s2 += __shfl_xor_sync(0xffffffffu, s2, o);
    if ((tid & 31) == 0) red[tid >> 5] = s2;
    __syncthreads();
    if (tid == 0) {
        float t = 0.f;
#pragma unroll
        for (int i = 0; i < 8; i++) t += red[i];
        stat[1] = rsqrtf(t * (1.f / DMODEL) + eps);
    }
    __syncthreads();
    const float rstd = stat[1];

#pragma unroll
    for (int i = 0; i < 4; i++) {
        const int c = tid + 256 * i;
        orow[c] = (v[i] - mu) * rstd * g[c] + b[c];
    }
}

// =====================================================================
// Tensor-core GEMM with 2-term bf16 split (error-compensated):
//   x = hi + lo (both bf16); C = Ah*Bh + Ah*Bl + Al*Bh  (fp32 accumulate)
//   dropped terms ~2^-18 relative -> rel_err ~1e-5 per GEMM.
// 128x128 block tile, BK=16, 256 threads (8 warps as 2m x 4n, 64x32 each),
// mma.sync.m16n8k16.bf16, double-buffered smem, LDSM fragment loads.
//   MODE 0: C = AB      MODE 1: C = AB + res
//   MODE 2: C = relu(AB + bias)   MODE 3: C = AB + bias + res
// M,N multiples of 128; K multiple of 16 (true at all call sites).
// =====================================================================
#define BK     16
#define APITCH 24    // bf16 pitch; 16B-chunk stride = 3 (odd) -> ldsm conflict-free
#define BPITCH 136   // bf16 pitch; 16B-chunk stride = 17 (odd) -> ldsm conflict-free

__device__ __forceinline__ uint32_t smem_u32(const void* p) {
    return (uint32_t)__cvta_generic_to_shared(p);
}
__device__ __forceinline__ void ldsm_x4(uint32_t& r0, uint32_t& r1, uint32_t& r2,
                                        uint32_t& r3, uint32_t a) {
    asm volatile("ldmatrix.sync.aligned.m8n8.x4.shared.b16 {%0,%1,%2,%3}, [%4];\n"
                 : "=r"(r0), "=r"(r1), "=r"(r2), "=r"(r3) : "r"(a));
}
__device__ __forceinline__ void ldsm_x4t(uint32_t& r0, uint32_t& r1, uint32_t& r2,
                                         uint32_t& r3, uint32_t a) {
    asm volatile("ldmatrix.sync.aligned.m8n8.x4.trans.shared.b16 {%0,%1,%2,%3}, [%4];\n"
                 : "=r"(r0), "=r"(r1), "=r"(r2), "=r"(r3) : "r"(a));
}
__device__ __forceinline__ void mma16816(float* d, const uint32_t* a, const uint32_t* b) {
    asm volatile(
        "mma.sync.aligned.m16n8k16.row.col.f32.bf16.bf16.f32 "
        "{%0,%1,%2,%3}, {%4,%5,%6,%7}, {%8,%9}, {%0,%1,%2,%3};\n"
        : "+f"(d[0]), "+f"(d[1]), "+f"(d[2]), "+f"(d[3])
        : "r"(a[0]), "r"(a[1]), "r"(a[2]), "r"(a[3]), "r"(b[0]), "r"(b[1]));
}

// split 4 fp32 -> (hi,lo) bf16, store packed (hi as uint2, lo as uint2)
__device__ __forceinline__ void split_store4(__nv_bfloat16* hB, __nv_bfloat16* lB,
                                             int idx, float4 f) {
    float v[4] = {f.x, f.y, f.z, f.w};
    uint16_t hs[4], ls[4];
#pragma unroll
    for (int i = 0; i < 4; i++) {
        __nv_bfloat16 h = __float2bfloat16(v[i]);
        float r = v[i] - __bfloat162float(h);
        __nv_bfloat16 l = __float2bfloat16(r);
        hs[i] = __bfloat16_as_ushort(h);
        ls[i] = __bfloat16_as_ushort(l);
    }
    uint2 hp, lp;
    hp.x = (uint32_t)hs[0] | ((uint32_t)hs[1] << 16);
    hp.y = (uint32_t)hs[2] | ((uint32_t)hs[3] << 16);
    lp.x = (uint32_t)ls[0] | ((uint32_t)ls[1] << 16);
    lp.y = (uint32_t)ls[2] | ((uint32_t)ls[3] << 16);
    *(uint2*)&hB[idx] = hp;
    *(uint2*)&lB[idx] = lp;
}

template <int MODE>
__device__ __forceinline__
void mma_gemm_body(const float* __restrict__ A, const float* __restrict__ B,
                   const float* __restrict__ bias, const float* res,
                   float* C, int M, int N, int K, int bm, int bn)
{
    __shared__ __nv_bfloat16 Ah[2][128 * APITCH];
    __shared__ __nv_bfloat16 Al[2][128 * APITCH];
    __shared__ __nv_bfloat16 Bh[2][BK * BPITCH];
    __shared__ __nv_bfloat16 Bl[2][BK * BPITCH];

    const int tid  = threadIdx.x;
    const int lane = tid & 31;
    const int warp = tid >> 5;
    const int wm   = (warp >> 2) * 64;   // warp m-offset in block tile
    const int wn   = (warp & 3) * 32;    // warp n-offset

    float acc[4][4][4];
#pragma unroll
    for (int i = 0; i < 4; i++)
#pragma unroll
        for (int j = 0; j < 4; j++)
#pragma unroll
            for (int r = 0; r < 4; r++) acc[i][j][r] = 0.f;

    // loader indices: A tile 128x16 (thread: rows ar, ar+64; 4 cols), B tile 16x128
    const int ar   = tid >> 2;
    const int ac   = (tid & 3) * 4;
    const int brow = tid >> 4;          // 0..15
    const int bcol = (tid & 15) * 8;    // 0..120

    const float* Ap = A + (size_t)bm * K;
    const float* Bp = B + bn;

    // fragment lane offsets (bytes)
    const uint32_t a_off = (uint32_t)(((lane & 15) * APITCH + (lane >> 4) * 8) * 2);
    const uint32_t b_off = (uint32_t)((((lane & 7) + ((lane >> 3) & 1) * 8) * BPITCH
                                       + (lane >> 4) * 8) * 2);
    uint32_t uAh[2], uAl[2], uBh[2], uBl[2];
#pragma unroll
    for (int b = 0; b < 2; b++) {
        uAh[b] = smem_u32(&Ah[b][0]);
        uAl[b] = smem_u32(&Al[b][0]);
        uBh[b] = smem_u32(&Bh[b][0]);
        uBl[b] = smem_u32(&Bl[b][0]);
    }

    // --- preload tile 0 ---
    float4 fa0 = *(const float4*)(Ap + (size_t)ar * K + ac);
    float4 fa1 = *(const float4*)(Ap + (size_t)(ar + 64) * K + ac);
    float4 fb0 = *(const float4*)(Bp + (size_t)brow * N + bcol);
    float4 fb1 = *(const float4*)(Bp + (size_t)brow * N + bcol + 4);
    split_store4(Ah[0], Al[0], ar * APITCH + ac, fa0);
    split_store4(Ah[0], Al[0], (ar + 64) * APITCH + ac, fa1);
    split_store4(Bh[0], Bl[0], brow * BPITCH + bcol, fb0);
    split_store4(Bh[0], Bl[0], brow * BPITCH + bcol + 4, fb1);
    __syncthreads();

    int buf = 0;
    for (int k0 = 0; k0 < K; k0 += BK) {
        const bool has_next = (k0 + BK) < K;
        if (has_next) {
            const int kn = k0 + BK;
            fa0 = *(const float4*)(Ap + (size_t)ar * K + kn + ac);
            fa1 = *(const float4*)(Ap + (size_t)(ar + 64) * K + kn + ac);
            fb0 = *(const float4*)(Bp + (size_t)(kn + brow) * N + bcol);
            fb1 = *(const float4*)(Bp + (size_t)(kn + brow) * N + bcol + 4);
        }

        // B fragments for 4 n-tiles (hi and lo): two x4.trans each
        uint32_t bh[4][2], bl[4][2];
#pragma unroll
        for (int jp = 0; jp < 2; jp++) {
            const uint32_t nb = (uint32_t)((wn + 16 * jp) * 2);
            ldsm_x4t(bh[2 * jp][0], bh[2 * jp][1], bh[2 * jp + 1][0], bh[2 * jp + 1][1],
                     uBh[buf] + b_off + nb);
            ldsm_x4t(bl[2 * jp][0], bl[2 * jp][1], bl[2 * jp + 1][0], bl[2 * jp + 1][1],
                     uBl[buf] + b_off + nb);
        }

#pragma unroll
        for (int i = 0; i < 4; i++) {
            const uint32_t mb = (uint32_t)((wm + 16 * i) * APITCH * 2);
            uint32_t ah[4], al[4];
            ldsm_x4(ah[0], ah[1], ah[2], ah[3], uAh[buf] + a_off + mb);
            ldsm_x4(al[0], al[1], al[2], al[3], uAl[buf] + a_off + mb);
#pragma unroll
            for (int j = 0; j < 4; j++) {
                mma16816(acc[i][j], ah, bh[j]);
                mma16816(acc[i][j], ah, bl[j]);
                mma16816(acc[i][j], al, bh[j]);
            }
        }

        if (has_next) {
            const int nb = buf ^ 1;
            split_store4(Ah[nb], Al[nb], ar * APITCH + ac, fa0);
            split_store4(Ah[nb], Al[nb], (ar + 64) * APITCH + ac, fa1);
            split_store4(Bh[nb], Bl[nb], brow * BPITCH + bcol, fb0);
            split_store4(Bh[nb], Bl[nb], brow * BPITCH + bcol + 4, fb1);
        }
        __syncthreads();
        buf ^= 1;
    }

    // epilogue: per mma tile, thread owns (row, col..col+1) and (row+8, ...)
    const int r0 = lane >> 2;
    const int c0 = (lane & 3) * 2;
#pragma unroll
    for (int i = 0; i < 4; i++) {
        const int row = bm + wm + 16 * i + r0;
#pragma unroll
        for (int j = 0; j < 4; j++) {
            const int col = bn + wn + 8 * j + c0;
#pragma unroll
            for (int h = 0; h < 2; h++) {
                const size_t off = (size_t)(row + 8 * h) * N + col;
                float v0 = acc[i][j][2 * h + 0];
                float v1 = acc[i][j][2 * h + 1];
                if (MODE == 1) { v0 += res[off]; v1 += res[off + 1]; }
                if (MODE == 2) {
                    v0 = fmaxf(v0 + bias[col], 0.f);
                    v1 = fmaxf(v1 + bias[col + 1], 0.f);
                }
                if (MODE == 3) {
                    v0 += bias[col] + res[off];
                    v1 += bias[col + 1] + res[off + 1];
                }
                float2 o; o.x = v0; o.y = v1;
                *(float2*)&C[off] = o;
            }
        }
    }
}

template <int MODE>
__global__ __launch_bounds__(256)
void mma_gemm_kernel(const float* __restrict__ A, const float* __restrict__ B,
                     const float* __restrict__ bias, const float* res,
                     float* C, int M, int N, int K)
{
    mma_gemm_body<MODE>(A, B, bias, res, C, M, N, K,
                        blockIdx.y * 128, blockIdx.x * 128);
}

// Fused QKV: blockIdx.z picks (W, out)
__global__ __launch_bounds__(256)
void mma_qkv_kernel(const float* __restrict__ A,
                    const float* __restrict__ B0, const float* __restrict__ B1,
                    const float* __restrict__ B2,
                    float* C0, float* C1, float* C2)
{
    const float* B = (blockIdx.z == 0) ? B0 : (blockIdx.z == 1) ? B1 : B2;
    float*       C = (blockIdx.z == 0) ? C0 : (blockIdx.z == 1) ? C1 : C2;
    mma_gemm_body<0>(A, B, nullptr, nullptr, C, NTOK, DMODEL, DMODEL,
                     blockIdx.y * 128, blockIdx.x * 128);
}

// =====================================================================
// Flash attention, fp32 (unchanged from the passing R7 kernel).
// =====================================================================
#define ATT_SMEM_FLOATS (64 * 64 + 64 * 68 + 64 * 64 + 64 * 65)
#define ATT_SMEM_BYTES  (ATT_SMEM_FLOATS * 4)

__global__ __launch_bounds__(256)
void attn_kernel(const float* __restrict__ Q, const float* __restrict__ Kg,
                 const float* __restrict__ Vg, float* __restrict__ O)
{
    extern __shared__ float sm[];
    float (*Qs)[64] = (float (*)[64])sm;
    float (*Ks)[68] = (float (*)[68])(sm + 64 * 64);
    float (*Vs)[64] = (float (*)[64])(sm + 64 * 64 + 64 * 68);
    float (*Ps)[65] = (float (*)[65])(sm + 64 * 64 + 64 * 68 + 64 * 64);

    const int tid = threadIdx.x;
    const int tx = tid & 15;
    const int ty = tid >> 4;
    const int qt = blockIdx.x;
    const int bh = blockIdx.y;
    const size_t base = ((size_t)(bh >> 4) * 2048) * DMODEL + (size_t)(bh & 15) * 64;
    const float* Qp = Q  + base + (size_t)qt * 64 * DMODEL;
    const float* Kp = Kg + base;
    const float* Vp = Vg + base;
    float*       Op = O  + base + (size_t)qt * 64 * DMODEL;

    {
        const int r0 = tid >> 4;
        const int d  = (tid & 15) * 4;
#pragma unroll
        for (int it = 0; it < 4; it++) {
            const int r = r0 + it * 16;
            float4 f = *(const float4*)(Qp + (size_t)r * DMODEL + d);
            Qs[r][d + 0] = f.x * 0.125f;
            Qs[r][d + 1] = f.y * 0.125f;
            Qs[r][d + 2] = f.z * 0.125f;
            Qs[r][d + 3] = f.w * 0.125f;
        }
    }

    float acc[4][4];
#pragma unroll
    for (int i = 0; i < 4; i++)
#pragma unroll
        for (int j = 0; j < 4; j++) acc[i][j] = 0.f;
    float mrun[4], lrun[4];
#pragma unroll
    for (int i = 0; i < 4; i++) { mrun[i] = -1e30f; lrun[i] = 0.f; }

    for (int kt = 0; kt < 32; kt++) {
        __syncthreads();
        {
            const float* Kt = Kp + (size_t)(kt * 64) * DMODEL;
            const float* Vt = Vp + (size_t)(kt * 64) * DMODEL;
            const int r0 = tid >> 4;
            const int d  = (tid & 15) * 4;
#pragma unroll
            for (int it = 0; it < 4; it++) {
                const int r = r0 + it * 16;
                *(float4*)&Ks[r][d] = *(const float4*)(Kt + (size_t)r * DMODEL + d);
                *(float4*)&Vs[r][d] = *(const float4*)(Vt + (size_t)r * DMODEL + d);
            }
        }
        __syncthreads();

        float s[4][4];
#pragma unroll
        for (int i = 0; i < 4; i++)
#pragma unroll
            for (int j = 0; j < 4; j++) s[i][j] = 0.f;
#pragma unroll
        for (int d = 0; d < 64; d += 4) {
            float4 a[4], b[4];
#pragma unroll
            for (int i = 0; i < 4; i++) a[i] = *(const float4*)&Qs[ty + 16 * i][d];
#pragma unroll
            for (int j = 0; j < 4; j++) b[j] = *(const float4*)&Ks[tx + 16 * j][d];
#pragma unroll
            for (int i = 0; i < 4; i++)
#pragma unroll
                for (int j = 0; j < 4; j++) {
                    s[i][j] += a[i].x * b[j].x;
                    s[i][j] += a[i].y * b[j].y;
                    s[i][j] += a[i].z * b[j].z;
                    s[i][j] += a[i].w * b[j].w;
                }
        }

#pragma unroll
        for (int i = 0; i < 4; i++) {
            float mt = fmaxf(fmaxf(s[i][0], s[i][1]), fmaxf(s[i][2], s[i][3]));
#pragma unroll
            for (int o = 8; o; o >>= 1) mt = fmaxf(mt, __shfl_xor_sync(0xffffffffu, mt, o));
            const float mnew = fmaxf(mrun[i], mt);
            const float corr = __expf(mrun[i] - mnew);
            mrun[i] = mnew;
            float p[4];
            float ls = 0.f;
#pragma unroll
            for (int j = 0; j < 4; j++) { p[j] = __expf(s[i][j] - mnew); ls += p[j]; }
#pragma unroll
            for (int o = 8; o; o >>= 1) ls += __shfl_xor_sync(0xffffffffu, ls, o);
            lrun[i] = lrun[i] * corr + ls;
#pragma unroll
            for (int j = 0; j < 4; j++) acc[i][j] *= corr;
#pragma unroll
            for (int j = 0; j < 4; j++) Ps[ty + 16 * i][tx + 16 * j] = p[j];
        }
        __syncthreads();

#pragma unroll 8
        for (int k = 0; k < 64; k++) {
            float pv[4], vv[4];
#pragma unroll
            for (int i = 0; i < 4; i++) pv[i] = Ps[ty + 16 * i][k];
#pragma unroll
            for (int j = 0; j < 4; j++) vv[j] = Vs[k][tx + 16 * j];
#pragma unroll
            for (int i = 0; i < 4; i++)
#pragma unroll
                for (int j = 0; j < 4; j++) acc[i][j] += pv[i] * vv[j];
        }
    }

#pragma unroll
    for (int i = 0; i < 4; i++) {
        const float inv = 1.f / lrun[i];
#pragma unroll
        for (int j = 0; j < 4; j++)
            Op[(size_t)(ty + 16 * i) * DMODEL + tx + 16 * j] = acc[i][j] * inv;
    }
}

// =====================================================================
// launch
// =====================================================================
extern "C" void kernel_launch(void* const* d_in, const int* in_sizes, int n_in,
                              void* d_out, int out_size)
{
    (void)in_sizes; (void)n_in; (void)out_size;
    const float* x    = (const float*)d_in[0];
    const float* Wq   = (const float*)d_in[1];
    const float* Wk   = (const float*)d_in[2];
    const float* Wv   = (const float*)d_in[3];
    const float* Wo   = (const float*)d_in[4];
    const float* ln1g = (const float*)d_in[5];
    const float* ln1b = (const float*)d_in[6];
    const float* fc1w = (const float*)d_in[7];
    const float* fc1b = (const float*)d_in[8];
    const float* fc2w = (const float*)d_in[9];
    const float* fc2b = (const float*)d_in[10];
    const float* ln2g = (const float*)d_in[11];
    const float* ln2b = (const float*)d_in[12];
    float* out = (float*)d_out;

    void *pxn, *pq, *pk, *pv, *patt, *ph, *pff;
    cudaGetSymbolAddress(&pxn,  g_xn);
    cudaGetSymbolAddress(&pq,   g_q);
    cudaGetSymbolAddress(&pk,   g_k);
    cudaGetSymbolAddress(&pv,   g_v);
    cudaGetSymbolAddress(&patt, g_att);
    cudaGetSymbolAddress(&ph,   g_h);
    cudaGetSymbolAddress(&pff,  g_ff);
    float* xn  = (float*)pxn;
    float* q   = (float*)pq;
    float* k   = (float*)pk;
    float* v   = (float*)pv;
    float* att = (float*)patt;
    float* h   = (float*)ph;
    float* ff  = (float*)pff;

    cudaFuncSetAttribute(attn_kernel, cudaFuncAttributeMaxDynamicSharedMemorySize,
                         ATT_SMEM_BYTES);

    // 1) LN1
    ln_kernel<<<NTOK, 256>>>(x, ln1g, ln1b, 1e-5f, xn);

    // 2) fused QKV projections (tensor core, split-bf16)
    dim3 gQKV(DMODEL / 128, NTOK / 128, 3);   // (8, 64, 3)
    mma_qkv_kernel<<<gQKV, 256>>>(xn, Wq, Wk, Wv, q, k, v);

    // 3) attention (flash, fp32)
    attn_kernel<<<dim3(32, 64), 256, ATT_SMEM_BYTES>>>(q, k, v, att);

    // 4) out = att @ Wo + x
    dim3 gD(DMODEL / 128, NTOK / 128);        // (8, 64)
    mma_gemm_kernel<1><<<gD, 256>>>(att, Wo, nullptr, x, out, NTOK, DMODEL, DMODEL);

    // 5) LN2 (eps = 1e-6)
    ln_kernel<<<NTOK, 256>>>(out, ln2g, ln2b, 1e-6f, h);

    // 6) ff = relu(h @ fc1_w + fc1_b)
    dim3 gF(NFF / 128, NTOK / 128);           // (16, 64)
    mma_gemm_kernel<2><<<gF, 256>>>(h, fc1w, fc1b, nullptr, ff, NTOK, NFF, DMODEL);

    // 7) d_out = d_out + ff @ fc2_w + fc2_b
    mma_gemm_kernel<3><<<gD, 256>>>(ff, fc2w, fc2b, out, out, NTOK, DMODEL, NFF);
}

// round 10
// speedup vs baseline: 2.3418x; 1.4289x over previous
#include <cuda_runtime.h>
#include <cuda_bf16.h>
#include <cstdint>
#include <cstddef>

#define NTOK   8192      // B*S
#define DMODEL 1024
#define NFF    2048

// ---------------- scratch (no allocations allowed -> device globals) ----------------
__device__ float g_xn [NTOK * DMODEL];
__device__ float g_q  [NTOK * DMODEL];
__device__ float g_k  [NTOK * DMODEL];
__device__ float g_v  [NTOK * DMODEL];
__device__ float g_att[NTOK * DMODEL];
__device__ float g_h  [NTOK * DMODEL];
__device__ float g_ff [NTOK * NFF];

// =====================================================================
// LayerNorm: one block per row (1024 elements), 256 threads x 4 elems
// =====================================================================
__global__ __launch_bounds__(256)
void ln_kernel(const float* __restrict__ x, const float* __restrict__ g,
               const float* __restrict__ b, float eps, float* __restrict__ out)
{
    const int tid = threadIdx.x;
    const float* xr = x + (size_t)blockIdx.x * DMODEL;
    float* orow = out + (size_t)blockIdx.x * DMODEL;

    float v[4];
    float s = 0.f;
#pragma unroll
    for (int i = 0; i < 4; i++) { v[i] = xr[tid + 256 * i]; s += v[i]; }

    __shared__ float red[8];
    __shared__ float stat[2];

#pragma unroll
    for (int o = 16; o; o >>= 1) s += __shfl_xor_sync(0xffffffffu, s, o);
    if ((tid & 31) == 0) red[tid >> 5] = s;
    __syncthreads();
    if (tid == 0) {
        float t = 0.f;
#pragma unroll
        for (int i = 0; i < 8; i++) t += red[i];
        stat[0] = t * (1.f / DMODEL);
    }
    __syncthreads();
    const float mu = stat[0];

    float s2 = 0.f;
#pragma unroll
    for (int i = 0; i < 4; i++) { float d = v[i] - mu; s2 += d * d; }
#pragma unroll
    for (int o = 16; o; o >>= 1) s2 += __shfl_xor_sync(0xffffffffu, s2, o);
    if ((tid & 31) == 0) red[tid >> 5] = s2;
    __syncthreads();
    if (tid == 0) {
        float t = 0.f;
#pragma unroll
        for (int i = 0; i < 8; i++) t += red[i];
        stat[1] = rsqrtf(t * (1.f / DMODEL) + eps);
    }
    __syncthreads();
    const float rstd = stat[1];

#pragma unroll
    for (int i = 0; i < 4; i++) {
        const int c = tid + 256 * i;
        orow[c] = (v[i] - mu) * rstd * g[c] + b[c];
    }
}

// =====================================================================
// mma helpers (shared by GEMM + attention)
// =====================================================================
#define BK     16
#define APITCH 24    // bf16 pitch; 16B-chunk stride = 3 (odd) -> ldsm conflict-free
#define BPITCH 136   // bf16 pitch; 16B-chunk stride = 17 (odd) -> ldsm conflict-free

__device__ __forceinline__ uint32_t smem_u32(const void* p) {
    return (uint32_t)__cvta_generic_to_shared(p);
}
__device__ __forceinline__ void ldsm_x4(uint32_t& r0, uint32_t& r1, uint32_t& r2,
                                        uint32_t& r3, uint32_t a) {
    asm volatile("ldmatrix.sync.aligned.m8n8.x4.shared.b16 {%0,%1,%2,%3}, [%4];\n"
                 : "=r"(r0), "=r"(r1), "=r"(r2), "=r"(r3) : "r"(a));
}
__device__ __forceinline__ void ldsm_x4t(uint32_t& r0, uint32_t& r1, uint32_t& r2,
                                         uint32_t& r3, uint32_t a) {
    asm volatile("ldmatrix.sync.aligned.m8n8.x4.trans.shared.b16 {%0,%1,%2,%3}, [%4];\n"
                 : "=r"(r0), "=r"(r1), "=r"(r2), "=r"(r3) : "r"(a));
}
__device__ __forceinline__ void mma16816(float* d, const uint32_t* a, const uint32_t* b) {
    asm volatile(
        "mma.sync.aligned.m16n8k16.row.col.f32.bf16.bf16.f32 "
        "{%0,%1,%2,%3}, {%4,%5,%6,%7}, {%8,%9}, {%0,%1,%2,%3};\n"
        : "+f"(d[0]), "+f"(d[1]), "+f"(d[2]), "+f"(d[3])
        : "r"(a[0]), "r"(a[1]), "r"(a[2]), "r"(a[3]), "r"(b[0]), "r"(b[1]));
}

// split 4 fp32 -> (hi,lo) bf16, store packed (hi as uint2, lo as uint2)
__device__ __forceinline__ void split_store4(__nv_bfloat16* hB, __nv_bfloat16* lB,
                                             int idx, float4 f) {
    float v[4] = {f.x, f.y, f.z, f.w};
    uint16_t hs[4], ls[4];
#pragma unroll
    for (int i = 0; i < 4; i++) {
        __nv_bfloat16 h = __float2bfloat16(v[i]);
        float r = v[i] - __bfloat162float(h);
        __nv_bfloat16 l = __float2bfloat16(r);
        hs[i] = __bfloat16_as_ushort(h);
        ls[i] = __bfloat16_as_ushort(l);
    }
    uint2 hp, lp;
    hp.x = (uint32_t)hs[0] | ((uint32_t)hs[1] << 16);
    hp.y = (uint32_t)hs[2] | ((uint32_t)hs[3] << 16);
    lp.x = (uint32_t)ls[0] | ((uint32_t)ls[1] << 16);
    lp.y = (uint32_t)ls[2] | ((uint32_t)ls[3] << 16);
    *(uint2*)&hB[idx] = hp;
    *(uint2*)&lB[idx] = lp;
}

// =====================================================================
// Tensor-core GEMM, split-bf16 (C = Ah*Bh + Ah*Bl + Al*Bh), fp32 accum.
//   MODE 0: C=AB  1: C=AB+res  2: C=relu(AB+bias)  3: C=AB+bias+res
// 128x128 tile, BK=16, 256 threads, double-buffered smem. (unchanged, proven)
// =====================================================================
template <int MODE>
__device__ __forceinline__
void mma_gemm_body(const float* __restrict__ A, const float* __restrict__ B,
                   const float* __restrict__ bias, const float* res,
                   float* C, int M, int N, int K, int bm, int bn)
{
    __shared__ __nv_bfloat16 Ah[2][128 * APITCH];
    __shared__ __nv_bfloat16 Al[2][128 * APITCH];
    __shared__ __nv_bfloat16 Bh[2][BK * BPITCH];
    __shared__ __nv_bfloat16 Bl[2][BK * BPITCH];

    const int tid  = threadIdx.x;
    const int lane = tid & 31;
    const int warp = tid >> 5;
    const int wm   = (warp >> 2) * 64;
    const int wn   = (warp & 3) * 32;

    float acc[4][4][4];
#pragma unroll
    for (int i = 0; i < 4; i++)
#pragma unroll
        for (int j = 0; j < 4; j++)
#pragma unroll
            for (int r = 0; r < 4; r++) acc[i][j][r] = 0.f;

    const int ar   = tid >> 2;
    const int ac   = (tid & 3) * 4;
    const int brow = tid >> 4;
    const int bcol = (tid & 15) * 8;

    const float* Ap = A + (size_t)bm * K;
    const float* Bp = B + bn;

    const uint32_t a_off = (uint32_t)(((lane & 15) * APITCH + (lane >> 4) * 8) * 2);
    const uint32_t b_off = (uint32_t)((((lane & 7) + ((lane >> 3) & 1) * 8) * BPITCH
                                       + (lane >> 4) * 8) * 2);
    uint32_t uAh[2], uAl[2], uBh[2], uBl[2];
#pragma unroll
    for (int b = 0; b < 2; b++) {
        uAh[b] = smem_u32(&Ah[b][0]);
        uAl[b] = smem_u32(&Al[b][0]);
        uBh[b] = smem_u32(&Bh[b][0]);
        uBl[b] = smem_u32(&Bl[b][0]);
    }

    float4 fa0 = *(const float4*)(Ap + (size_t)ar * K + ac);
    float4 fa1 = *(const float4*)(Ap + (size_t)(ar + 64) * K + ac);
    float4 fb0 = *(const float4*)(Bp + (size_t)brow * N + bcol);
    float4 fb1 = *(const float4*)(Bp + (size_t)brow * N + bcol + 4);
    split_store4(Ah[0], Al[0], ar * APITCH + ac, fa0);
    split_store4(Ah[0], Al[0], (ar + 64) * APITCH + ac, fa1);
    split_store4(Bh[0], Bl[0], brow * BPITCH + bcol, fb0);
    split_store4(Bh[0], Bl[0], brow * BPITCH + bcol + 4, fb1);
    __syncthreads();

    int buf = 0;
    for (int k0 = 0; k0 < K; k0 += BK) {
        const bool has_next = (k0 + BK) < K;
        if (has_next) {
            const int kn = k0 + BK;
            fa0 = *(const float4*)(Ap + (size_t)ar * K + kn + ac);
            fa1 = *(const float4*)(Ap + (size_t)(ar + 64) * K + kn + ac);
            fb0 = *(const float4*)(Bp + (size_t)(kn + brow) * N + bcol);
            fb1 = *(const float4*)(Bp + (size_t)(kn + brow) * N + bcol + 4);
        }

        uint32_t bh[4][2], bl[4][2];
#pragma unroll
        for (int jp = 0; jp < 2; jp++) {
            const uint32_t nb = (uint32_t)((wn + 16 * jp) * 2);
            ldsm_x4t(bh[2 * jp][0], bh[2 * jp][1], bh[2 * jp + 1][0], bh[2 * jp + 1][1],
                     uBh[buf] + b_off + nb);
            ldsm_x4t(bl[2 * jp][0], bl[2 * jp][1], bl[2 * jp + 1][0], bl[2 * jp + 1][1],
                     uBl[buf] + b_off + nb);
        }

#pragma unroll
        for (int i = 0; i < 4; i++) {
            const uint32_t mb = (uint32_t)((wm + 16 * i) * APITCH * 2);
            uint32_t ah[4], al[4];
            ldsm_x4(ah[0], ah[1], ah[2], ah[3], uAh[buf] + a_off + mb);
            ldsm_x4(al[0], al[1], al[2], al[3], uAl[buf] + a_off + mb);
#pragma unroll
            for (int j = 0; j < 4; j++) {
                mma16816(acc[i][j], ah, bh[j]);
                mma16816(acc[i][j], ah, bl[j]);
                mma16816(acc[i][j], al, bh[j]);
            }
        }

        if (has_next) {
            const int nb = buf ^ 1;
            split_store4(Ah[nb], Al[nb], ar * APITCH + ac, fa0);
            split_store4(Ah[nb], Al[nb], (ar + 64) * APITCH + ac, fa1);
            split_store4(Bh[nb], Bl[nb], brow * BPITCH + bcol, fb0);
            split_store4(Bh[nb], Bl[nb], brow * BPITCH + bcol + 4, fb1);
        }
        __syncthreads();
        buf ^= 1;
    }

    const int r0 = lane >> 2;
    const int c0 = (lane & 3) * 2;
#pragma unroll
    for (int i = 0; i < 4; i++) {
        const int row = bm + wm + 16 * i + r0;
#pragma unroll
        for (int j = 0; j < 4; j++) {
            const int col = bn + wn + 8 * j + c0;
#pragma unroll
            for (int h = 0; h < 2; h++) {
                const size_t off = (size_t)(row + 8 * h) * N + col;
                float v0 = acc[i][j][2 * h + 0];
                float v1 = acc[i][j][2 * h + 1];
                if (MODE == 1) { v0 += res[off]; v1 += res[off + 1]; }
                if (MODE == 2) {
                    v0 = fmaxf(v0 + bias[col], 0.f);
                    v1 = fmaxf(v1 + bias[col + 1], 0.f);
                }
                if (MODE == 3) {
                    v0 += bias[col] + res[off];
                    v1 += bias[col + 1] + res[off + 1];
                }
                float2 o; o.x = v0; o.y = v1;
                *(float2*)&C[off] = o;
            }
        }
    }
}

template <int MODE>
__global__ __launch_bounds__(256)
void mma_gemm_kernel(const float* __restrict__ A, const float* __restrict__ B,
                     const float* __restrict__ bias, const float* res,
                     float* C, int M, int N, int K)
{
    mma_gemm_body<MODE>(A, B, bias, res, C, M, N, K,
                        blockIdx.y * 128, blockIdx.x * 128);
}

__global__ __launch_bounds__(256)
void mma_qkv_kernel(const float* __restrict__ A,
                    const float* __restrict__ B0, const float* __restrict__ B1,
                    const float* __restrict__ B2,
                    float* C0, float* C1, float* C2)
{
    const float* B = (blockIdx.z == 0) ? B0 : (blockIdx.z == 1) ? B1 : B2;
    float*       C = (blockIdx.z == 0) ? C0 : (blockIdx.z == 1) ? C1 : C2;
    mma_gemm_body<0>(A, B, nullptr, nullptr, C, NTOK, DMODEL, DMODEL,
                     blockIdx.y * 128, blockIdx.x * 128);
}

// =====================================================================
// Tensor-core flash attention, split-bf16 both matmuls.
// Block: 128 threads (4 warps), one (b,h) head, 64-query tile, Bc=64.
// Warp owns 16 q-rows x all 64 keys -> softmax is warp-local.
// smem pitch 72 halves (9x16B chunks, odd -> ldsm conflict-free).
//   Q,P as A-operand (ldsm_x4);  V as B-operand (ldsm_x4t, GEMM pattern);
//   K as B-operand via non-trans ldsm_x4 on [key][d] (tiles {r0,r2},{r1,r3}).
// =====================================================================
#define ATTP 72
#define ATT2_SMEM_BYTES (8 * 64 * ATTP * 2)   // Qh,Ql,Kh,Kl,Vh,Vl,Ph,Pl = 73728 B

__global__ __launch_bounds__(128)
void attn_mma_kernel(const float* __restrict__ Q, const float* __restrict__ Kg,
                     const float* __restrict__ Vg, float* __restrict__ O)
{
    extern __shared__ __nv_bfloat16 sh[];
    __nv_bfloat16* Qh = sh;
    __nv_bfloat16* Ql = sh + 1 * 64 * ATTP;
    __nv_bfloat16* Kh = sh + 2 * 64 * ATTP;
    __nv_bfloat16* Kl = sh + 3 * 64 * ATTP;
    __nv_bfloat16* Vh = sh + 4 * 64 * ATTP;
    __nv_bfloat16* Vl = sh + 5 * 64 * ATTP;
    __nv_bfloat16* Ph = sh + 6 * 64 * ATTP;
    __nv_bfloat16* Pl = sh + 7 * 64 * ATTP;

    const int tid  = threadIdx.x;
    const int lane = tid & 31;
    const int warp = tid >> 5;
    const int qt   = blockIdx.x;            // 0..31
    const int bh   = blockIdx.y;            // 0..63
    const size_t base = ((size_t)(bh >> 4) * 2048) * DMODEL + (size_t)(bh & 15) * 64;
    const float* Qp = Q  + base + (size_t)qt * 64 * DMODEL;
    const float* Kp = Kg + base;
    const float* Vp = Vg + base;
    float*       Op = O  + base + (size_t)qt * 64 * DMODEL;

    // cooperative loader mapping: thread -> row lr (0..63), 32-col group lc
    const int lr = tid >> 1;
    const int lc = (tid & 1) * 32;

    // load + prescale + split Q (visible after iter-0's barriers)
    {
        float4 t[8];
#pragma unroll
        for (int i = 0; i < 8; i++)
            t[i] = *(const float4*)(Qp + (size_t)lr * DMODEL + lc + 4 * i);
#pragma unroll
        for (int i = 0; i < 8; i++) {
            t[i].x *= 0.125f; t[i].y *= 0.125f; t[i].z *= 0.125f; t[i].w *= 0.125f;
            split_store4(Qh, Ql, lr * ATTP + lc + 4 * i, t[i]);
        }
    }

    const uint32_t uQh = smem_u32(Qh), uQl = smem_u32(Ql);
    const uint32_t uKh = smem_u32(Kh), uKl = smem_u32(Kl);
    const uint32_t uVh = smem_u32(Vh), uVl = smem_u32(Vl);
    const uint32_t uPh = smem_u32(Ph), uPl = smem_u32(Pl);

    const uint32_t frag_a = (uint32_t)(((lane & 15) * ATTP + (lane >> 4) * 8) * 2);
    const uint32_t frag_b = (uint32_t)((((lane & 7) + ((lane >> 3) & 1) * 8) * ATTP
                                        + (lane >> 4) * 8) * 2);
    const uint32_t warp_m = (uint32_t)(warp * 16 * ATTP * 2);

    float o[8][4];
#pragma unroll
    for (int j = 0; j < 8; j++)
#pragma unroll
        for (int r = 0; r < 4; r++) o[j][r] = 0.f;
    float mrun[2] = {-1e30f, -1e30f};
    float lrun[2] = {0.f, 0.f};

    for (int kt = 0; kt < 32; kt++) {
        __syncthreads();   // all warps done reading K/V of previous tile
        {
            const float* Kt = Kp + (size_t)(kt * 64 + lr) * DMODEL + lc;
            const float* Vt = Vp + (size_t)(kt * 64 + lr) * DMODEL + lc;
            float4 a[8], b[8];
#pragma unroll
            for (int i = 0; i < 8; i++) a[i] = *(const float4*)(Kt + 4 * i);
#pragma unroll
            for (int i = 0; i < 8; i++) b[i] = *(const float4*)(Vt + 4 * i);
#pragma unroll
            for (int i = 0; i < 8; i++)
                split_store4(Kh, Kl, lr * ATTP + lc + 4 * i, a[i]);
#pragma unroll
            for (int i = 0; i < 8; i++)
                split_store4(Vh, Vl, lr * ATTP + lc + 4 * i, b[i]);
        }
        __syncthreads();   // K/V (and, on iter 0, Q) visible

        // ---- S = Q @ K^T (prescaled) ----
        float s[8][4];
#pragma unroll
        for (int j = 0; j < 8; j++)
#pragma unroll
            for (int r = 0; r < 4; r++) s[j][r] = 0.f;

#pragma unroll
        for (int ks = 0; ks < 4; ks++) {
            const uint32_t ko = (uint32_t)(ks * 32);   // 16 halves = 32 bytes
            uint32_t qh[4], ql[4];
            ldsm_x4(qh[0], qh[1], qh[2], qh[3], uQh + frag_a + warp_m + ko);
            ldsm_x4(ql[0], ql[1], ql[2], ql[3], uQl + frag_a + warp_m + ko);
#pragma unroll
            for (int jp = 0; jp < 4; jp++) {
                const uint32_t nb = (uint32_t)(jp * 16 * ATTP * 2);
                uint32_t h0, h1, h2, h3, l0, l1, l2, l3;
                ldsm_x4(h0, h1, h2, h3, uKh + frag_a + nb + ko);
                ldsm_x4(l0, l1, l2, l3, uKl + frag_a + nb + ko);
                uint32_t bh0[2] = {h0, h2}, bh1[2] = {h1, h3};
                uint32_t bl0[2] = {l0, l2}, bl1[2] = {l1, l3};
                mma16816(s[2 * jp],     qh, bh0);
                mma16816(s[2 * jp],     qh, bl0);
                mma16816(s[2 * jp],     ql, bh0);
                mma16816(s[2 * jp + 1], qh, bh1);
                mma16816(s[2 * jp + 1], qh, bl1);
                mma16816(s[2 * jp + 1], ql, bh1);
            }
        }

        // ---- online softmax (warp-local rows) + P -> smem (split) ----
#pragma unroll
        for (int h = 0; h < 2; h++) {
            float mt = -1e30f;
#pragma unroll
            for (int j = 0; j < 8; j++)
                mt = fmaxf(mt, fmaxf(s[j][2 * h], s[j][2 * h + 1]));
            mt = fmaxf(mt, __shfl_xor_sync(0xffffffffu, mt, 1));
            mt = fmaxf(mt, __shfl_xor_sync(0xffffffffu, mt, 2));
            const float mnew = fmaxf(mrun[h], mt);
            const float corr = __expf(mrun[h] - mnew);
            mrun[h] = mnew;

            float ls = 0.f;
            const int prow = warp * 16 + (lane >> 2) + 8 * h;
            const int pcb  = 2 * (lane & 3);
#pragma unroll
            for (int j = 0; j < 8; j++) {
                float p0 = __expf(s[j][2 * h]     - mnew);
                float p1 = __expf(s[j][2 * h + 1] - mnew);
                ls += p0 + p1;
                // split to (hi, lo) bf16 and store packed pair
                __nv_bfloat16 h0 = __float2bfloat16(p0);
                __nv_bfloat16 h1 = __float2bfloat16(p1);
                float r0f = p0 - __bfloat162float(h0);
                float r1f = p1 - __bfloat162float(h1);
                __nv_bfloat16 l0b = __float2bfloat16(r0f);
                __nv_bfloat16 l1b = __float2bfloat16(r1f);
                uint32_t hp = (uint32_t)__bfloat16_as_ushort(h0)
                            | ((uint32_t)__bfloat16_as_ushort(h1) << 16);
                uint32_t lp = (uint32_t)__bfloat16_as_ushort(l0b)
                            | ((uint32_t)__bfloat16_as_ushort(l1b) << 16);
                const int idx = prow * ATTP + 8 * j + pcb;
                *(uint32_t*)&Ph[idx] = hp;
                *(uint32_t*)&Pl[idx] = lp;
            }
            ls += __shfl_xor_sync(0xffffffffu, ls, 1);
            ls += __shfl_xor_sync(0xffffffffu, ls, 2);
            lrun[h] = lrun[h] * corr + ls;
#pragma unroll
            for (int j = 0; j < 8; j++) {
                o[j][2 * h]     *= corr;
                o[j][2 * h + 1] *= corr;
            }
        }
        __syncwarp();   // P (warp-private rows) visible to this warp's ldsm

        // ---- O += P @ V ----
#pragma unroll
        for (int ks = 0; ks < 4; ks++) {
            const uint32_t ko  = (uint32_t)(ks * 32);            // A: key chunk
            const uint32_t kvo = (uint32_t)(ks * 16 * ATTP * 2); // B: key rows
            uint32_t ph[4], pl[4];
            ldsm_x4(ph[0], ph[1], ph[2], ph[3], uPh + frag_a + warp_m + ko);
            ldsm_x4(pl[0], pl[1], pl[2], pl[3], uPl + frag_a + warp_m + ko);
#pragma unroll
            for (int jp = 0; jp < 4; jp++) {
                const uint32_t nb = (uint32_t)(16 * jp * 2);
                uint32_t h0, h1, h2, h3, l0, l1, l2, l3;
                ldsm_x4t(h0, h1, h2, h3, uVh + frag_b + kvo + nb);
                ldsm_x4t(l0, l1, l2, l3, uVl + frag_b + kvo + nb);
                uint32_t bh0[2] = {h0, h1}, bh1[2] = {h2, h3};
                uint32_t bl0[2] = {l0, l1}, bl1[2] = {l2, l3};
                mma16816(o[2 * jp],     ph, bh0);
                mma16816(o[2 * jp],     ph, bl0);
                mma16816(o[2 * jp],     pl, bh0);
                mma16816(o[2 * jp + 1], ph, bh1);
                mma16816(o[2 * jp + 1], ph, bl1);
                mma16816(o[2 * jp + 1], pl, bh1);
            }
        }
    }

    // ---- epilogue: O / l ----
#pragma unroll
    for (int h = 0; h < 2; h++) {
        const float inv = 1.f / lrun[h];
        const int row = warp * 16 + (lane >> 2) + 8 * h;
#pragma unroll
        for (int j = 0; j < 8; j++) {
            const int col = 8 * j + 2 * (lane & 3);
            float2 w;
            w.x = o[j][2 * h]     * inv;
            w.y = o[j][2 * h + 1] * inv;
            *(float2*)&Op[(size_t)row * DMODEL + col] = w;
        }
    }
}

// =====================================================================
// launch
// =====================================================================
extern "C" void kernel_launch(void* const* d_in, const int* in_sizes, int n_in,
                              void* d_out, int out_size)
{
    (void)in_sizes; (void)n_in; (void)out_size;
    const float* x    = (const float*)d_in[0];
    const float* Wq   = (const float*)d_in[1];
    const float* Wk   = (const float*)d_in[2];
    const float* Wv   = (const float*)d_in[3];
    const float* Wo   = (const float*)d_in[4];
    const float* ln1g = (const float*)d_in[5];
    const float* ln1b = (const float*)d_in[6];
    const float* fc1w = (const float*)d_in[7];
    const float* fc1b = (const float*)d_in[8];
    const float* fc2w = (const float*)d_in[9];
    const float* fc2b = (const float*)d_in[10];
    const float* ln2g = (const float*)d_in[11];
    const float* ln2b = (const float*)d_in[12];
    float* out = (float*)d_out;

    void *pxn, *pq, *pk, *pv, *patt, *ph, *pff;
    cudaGetSymbolAddress(&pxn,  g_xn);
    cudaGetSymbolAddress(&pq,   g_q);
    cudaGetSymbolAddress(&pk,   g_k);
    cudaGetSymbolAddress(&pv,   g_v);
    cudaGetSymbolAddress(&patt, g_att);
    cudaGetSymbolAddress(&ph,   g_h);
    cudaGetSymbolAddress(&pff,  g_ff);
    float* xn  = (float*)pxn;
    float* q   = (float*)pq;
    float* k   = (float*)pk;
    float* v   = (float*)pv;
    float* att = (float*)patt;
    float* h   = (float*)ph;
    float* ff  = (float*)pff;

    cudaFuncSetAttribute(attn_mma_kernel, cudaFuncAttributeMaxDynamicSharedMemorySize,
                         ATT2_SMEM_BYTES);

    // 1) LN1
    ln_kernel<<<NTOK, 256>>>(x, ln1g, ln1b, 1e-5f, xn);

    // 2) fused QKV projections (tensor core, split-bf16)
    dim3 gQKV(DMODEL / 128, NTOK / 128, 3);   // (8, 64, 3)
    mma_qkv_kernel<<<gQKV, 256>>>(xn, Wq, Wk, Wv, q, k, v);

    // 3) attention (flash, tensor core, split-bf16)
    attn_mma_kernel<<<dim3(32, 64), 128, ATT2_SMEM_BYTES>>>(q, k, v, att);

    // 4) out = att @ Wo + x
    dim3 gD(DMODEL / 128, NTOK / 128);        // (8, 64)
    mma_gemm_kernel<1><<<gD, 256>>>(att, Wo, nullptr, x, out, NTOK, DMODEL, DMODEL);

    // 5) LN2 (eps = 1e-6)
    ln_kernel<<<NTOK, 256>>>(out, ln2g, ln2b, 1e-6f, h);

    // 6) ff = relu(h @ fc1_w + fc1_b)
    dim3 gF(NFF / 128, NTOK / 128);           // (16, 64)
    mma_gemm_kernel<2><<<gF, 256>>>(h, fc1w, fc1b, nullptr, ff, NTOK, NFF, DMODEL);

    // 7) d_out = d_out + ff @ fc2_w + fc2_b
    mma_gemm_kernel<3><<<gD, 256>>>(ff, fc2w, fc2b, out, out, NTOK, DMODEL, NFF);
}